// round 9
// baseline (speedup 1.0000x reference)
#include <cuda_runtime.h>
#include <cstdint>

// SLayer: out[b,n] = sum_p exp(-(s0*(c0-x)^2 + s1*(c1-y)^2)) * mask[b,p]
// B=64, P=16384, N=64, D=2
constexpr int B_ = 64;
constexpr int P_ = 16384;
constexpr int N_ = 64;
constexpr int SPLITS = 9;
constexpr int CHUNK = (P_ + SPLITS - 1) / SPLITS;  // 1821
constexpr int NPW = 4;                 // n per warp; 8 warps * 4 = 32, z covers 2 halves
constexpr int NPAIR = NPW / 2;         // 2 packed pairs

__global__ void zero_out_kernel(float* out) {
    out[blockIdx.x * blockDim.x + threadIdx.x] = 0.0f;
}

__device__ __forceinline__ float ex2_approx(float x) {
    float r;
    asm("ex2.approx.ftz.f32 %0, %1;" : "=f"(r) : "f"(x));
    return r;
}

__device__ __forceinline__ uint64_t pack2(float lo, float hi) {
    uint64_t d;
    asm("mov.b64 %0, {%1, %2};" : "=l"(d) : "f"(lo), "f"(hi));
    return d;
}

__device__ __forceinline__ void unpack2(float& lo, float& hi, uint64_t v) {
    asm("mov.b64 {%0, %1}, %2;" : "=f"(lo), "=f"(hi) : "l"(v));
}

__device__ __forceinline__ uint64_t fma2(uint64_t a, uint64_t b, uint64_t c) {
    uint64_t d;
    asm("fma.rn.f32x2 %0, %1, %2, %3;" : "=l"(d) : "l"(a), "l"(b), "l"(c));
    return d;
}

__device__ __forceinline__ uint64_t mul2(uint64_t a, uint64_t b) {
    uint64_t d;
    asm("mul.rn.f32x2 %0, %1, %2;" : "=l"(d) : "l"(a), "l"(b));
    return d;
}

__device__ __forceinline__ uint64_t add2(uint64_t a, uint64_t b) {
    uint64_t d;
    asm("add.rn.f32x2 %0, %1, %2;" : "=l"(d) : "l"(a), "l"(b));
    return d;
}

__global__ __launch_bounds__(256, 5)
void rbf_pool_kernel(const float* __restrict__ batch,
                     const float* __restrict__ mask,
                     const float* __restrict__ centers,
                     const float* __restrict__ sharp,
                     float* __restrict__ out) {
    const int b    = blockIdx.x;
    const int s    = blockIdx.y;
    const int warp = threadIdx.x >> 5;
    const int lane = threadIdx.x & 31;
    const int n0   = blockIdx.z * 32 + warp * NPW;

    // exp(-expo) = 2^(A0*dx^2 + A1*dy^2), A = -log2(e)*s, dx = x - c0.
    const float L = -1.4426950408889634f;

    uint64_t nC0[NPAIR], nC1[NPAIR], A0p[NPAIR], A1p[NPAIR], acc[NPAIR];
#pragma unroll
    for (int j = 0; j < NPAIR; j++) {
        float nc0[2], nc1[2], a0[2], a1[2];
#pragma unroll
        for (int h = 0; h < 2; h++) {
            const int n = n0 + 2 * j + h;
            nc0[h] = -centers[n * 2 + 0];
            nc1[h] = -centers[n * 2 + 1];
            a0[h]  = L * sharp[n * 2 + 0];
            a1[h]  = L * sharp[n * 2 + 1];
        }
        nC0[j] = pack2(nc0[0], nc0[1]);
        nC1[j] = pack2(nc1[0], nc1[1]);
        A0p[j] = pack2(a0[0], a0[1]);
        A1p[j] = pack2(a1[0], a1[1]);
        acc[j] = 0ull;
    }

    const float2* pts = reinterpret_cast<const float2*>(batch) + (size_t)b * P_;
    const float*  msk = mask + (size_t)b * P_;
    const int start = s * CHUNK;
    const int end   = (start + CHUNK < P_) ? (start + CHUNK) : P_;

#pragma unroll 2
    for (int p = start + lane; p < end; p += 32) {
        const float2 xy = pts[p];
        const float  mm = msk[p];
        const uint64_t xb = pack2(xy.x, xy.x);
        const uint64_t yb = pack2(xy.y, xy.y);
        const uint64_t mb = pack2(mm, mm);
#pragma unroll
        for (int j = 0; j < NPAIR; j++) {
            const uint64_t dx = add2(xb, nC0[j]);
            const uint64_t dy = add2(yb, nC1[j]);
            const uint64_t t0 = mul2(A0p[j], dx);
            const uint64_t t1 = mul2(A1p[j], dy);
            uint64_t e = mul2(t0, dx);
            e = fma2(t1, dy, e);
            float elo, ehi;
            unpack2(elo, ehi, e);
            const uint64_t w = pack2(ex2_approx(elo), ex2_approx(ehi));
            acc[j] = fma2(w, mb, acc[j]);
        }
    }

    // warp tree-reduce each accumulator pair, lane 0 commits
#pragma unroll
    for (int j = 0; j < NPAIR; j++) {
        float vlo, vhi;
        unpack2(vlo, vhi, acc[j]);
#pragma unroll
        for (int o = 16; o > 0; o >>= 1) {
            vlo += __shfl_xor_sync(0xFFFFFFFFu, vlo, o);
            vhi += __shfl_xor_sync(0xFFFFFFFFu, vhi, o);
        }
        if (lane == 0) {
            atomicAdd(&out[b * N_ + n0 + 2 * j + 0], vlo);
            atomicAdd(&out[b * N_ + n0 + 2 * j + 1], vhi);
        }
    }
}

extern "C" void kernel_launch(void* const* d_in, const int* in_sizes, int n_in,
                              void* d_out, int out_size) {
    const float* batch   = (const float*)d_in[0];  // [64,16384,2]
    const float* mask    = (const float*)d_in[1];  // [64,16384]
    const float* centers = (const float*)d_in[2];  // [64,2]
    const float* sharp   = (const float*)d_in[3];  // [64,2]
    float* out = (float*)d_out;                    // [64,64]

    zero_out_kernel<<<16, 256>>>(out);             // 4096 elems
    dim3 grid(B_, SPLITS, 2);
    rbf_pool_kernel<<<grid, 256>>>(batch, mask, centers, sharp, out);
}

// round 10
// speedup vs baseline: 1.0460x; 1.0460x over previous
#include <cuda_runtime.h>
#include <cstdint>

// SLayer: out[b,n] = sum_p exp(-(s0*(c0-x)^2 + s1*(c1-y)^2)) * mask[b,p]
// B=64, P=16384, N=64, D=2
constexpr int B_ = 64;
constexpr int P_ = 16384;
constexpr int N_ = 64;
constexpr int SPLITS = 9;
constexpr int CHUNK = (P_ + SPLITS - 1) / SPLITS;  // 1821
constexpr int NPW = 4;                 // n per warp; 8 warps * 4 = 32, z covers 2 halves
constexpr int NPAIR = NPW / 2;         // 2 packed pairs

__global__ void zero_out_kernel(float* out) {
    out[blockIdx.x * blockDim.x + threadIdx.x] = 0.0f;
}

__device__ __forceinline__ float ex2_approx(float x) {
    float r;
    asm("ex2.approx.ftz.f32 %0, %1;" : "=f"(r) : "f"(x));
    return r;
}

__device__ __forceinline__ uint64_t pack2(float lo, float hi) {
    uint64_t d;
    asm("mov.b64 %0, {%1, %2};" : "=l"(d) : "f"(lo), "f"(hi));
    return d;
}

__device__ __forceinline__ void unpack2(float& lo, float& hi, uint64_t v) {
    asm("mov.b64 {%0, %1}, %2;" : "=f"(lo), "=f"(hi) : "l"(v));
}

__device__ __forceinline__ uint64_t fma2(uint64_t a, uint64_t b, uint64_t c) {
    uint64_t d;
    asm("fma.rn.f32x2 %0, %1, %2, %3;" : "=l"(d) : "l"(a), "l"(b), "l"(c));
    return d;
}

__device__ __forceinline__ uint64_t mul2(uint64_t a, uint64_t b) {
    uint64_t d;
    asm("mul.rn.f32x2 %0, %1, %2;" : "=l"(d) : "l"(a), "l"(b));
    return d;
}

__device__ __forceinline__ uint64_t add2(uint64_t a, uint64_t b) {
    uint64_t d;
    asm("add.rn.f32x2 %0, %1, %2;" : "=l"(d) : "l"(a), "l"(b));
    return d;
}

__global__ __launch_bounds__(256, 5)
void rbf_pool_kernel(const float* __restrict__ batch,
                     const float* __restrict__ mask,
                     const float* __restrict__ centers,
                     const float* __restrict__ sharp,
                     float* __restrict__ out) {
    const int b    = blockIdx.x;
    const int s    = blockIdx.y;
    const int warp = threadIdx.x >> 5;
    const int lane = threadIdx.x & 31;
    const int n0   = blockIdx.z * 32 + warp * NPW;

    // exp(-expo) = 2^(A0*dx^2 + A1*dy^2), A = -log2(e)*s, dx = x - c0.
    const float L = -1.4426950408889634f;

    uint64_t nC0[NPAIR], nC1[NPAIR], A0p[NPAIR], A1p[NPAIR], acc[NPAIR];
#pragma unroll
    for (int j = 0; j < NPAIR; j++) {
        float nc0[2], nc1[2], a0[2], a1[2];
#pragma unroll
        for (int h = 0; h < 2; h++) {
            const int n = n0 + 2 * j + h;
            nc0[h] = -centers[n * 2 + 0];
            nc1[h] = -centers[n * 2 + 1];
            a0[h]  = L * sharp[n * 2 + 0];
            a1[h]  = L * sharp[n * 2 + 1];
        }
        nC0[j] = pack2(nc0[0], nc0[1]);
        nC1[j] = pack2(nc1[0], nc1[1]);
        A0p[j] = pack2(a0[0], a0[1]);
        A1p[j] = pack2(a1[0], a1[1]);
        acc[j] = 0ull;
    }

    const float2* pts = reinterpret_cast<const float2*>(batch) + (size_t)b * P_;
    const float*  msk = mask + (size_t)b * P_;
    const int start = s * CHUNK;
    const int end   = (start + CHUNK < P_) ? (start + CHUNK) : P_;

#pragma unroll 2
    for (int p = start + lane; p < end; p += 32) {
        const float2 xy = pts[p];
        const float  mm = msk[p];
        const uint64_t xb = pack2(xy.x, xy.x);
        const uint64_t yb = pack2(xy.y, xy.y);
        const uint64_t mb = pack2(mm, mm);
#pragma unroll
        for (int j = 0; j < NPAIR; j++) {
            const uint64_t dx = add2(xb, nC0[j]);
            const uint64_t dy = add2(yb, nC1[j]);
            const uint64_t t0 = mul2(A0p[j], dx);
            const uint64_t t1 = mul2(A1p[j], dy);
            uint64_t e = mul2(t0, dx);
            e = fma2(t1, dy, e);
            float elo, ehi;
            unpack2(elo, ehi, e);
            const uint64_t w = pack2(ex2_approx(elo), ex2_approx(ehi));
            acc[j] = fma2(w, mb, acc[j]);
        }
    }

    // warp tree-reduce each accumulator pair, lane 0 commits
#pragma unroll
    for (int j = 0; j < NPAIR; j++) {
        float vlo, vhi;
        unpack2(vlo, vhi, acc[j]);
#pragma unroll
        for (int o = 16; o > 0; o >>= 1) {
            vlo += __shfl_xor_sync(0xFFFFFFFFu, vlo, o);
            vhi += __shfl_xor_sync(0xFFFFFFFFu, vhi, o);
        }
        if (lane == 0) {
            atomicAdd(&out[b * N_ + n0 + 2 * j + 0], vlo);
            atomicAdd(&out[b * N_ + n0 + 2 * j + 1], vhi);
        }
    }
}

extern "C" void kernel_launch(void* const* d_in, const int* in_sizes, int n_in,
                              void* d_out, int out_size) {
    const float* batch   = (const float*)d_in[0];  // [64,16384,2]
    const float* mask    = (const float*)d_in[1];  // [64,16384]
    const float* centers = (const float*)d_in[2];  // [64,2]
    const float* sharp   = (const float*)d_in[3];  // [64,2]
    float* out = (float*)d_out;                    // [64,64]

    zero_out_kernel<<<16, 256>>>(out);             // 4096 elems
    dim3 grid(B_, SPLITS, 2);
    rbf_pool_kernel<<<grid, 256>>>(batch, mask, centers, sharp, out);
}